// round 9
// baseline (speedup 1.0000x reference)
#include <cuda_runtime.h>
#include <cstdint>

#define Bb 8
#define Nn 4096
#define Cc 8
#define Tt 256
#define NPB 32                 // n-values per block in k_reduce
#define NBLK (Nn / NPB)        // 128 n-blocks per batch
#define TQ (Tt / 4)            // 64 float4 quads over t
#define KG 8                   // k's per block in k_sig
#define TI 16                  // output rows per block in k_attn
#define KC 16                  // k-rows per staged S chunk in k_attn
#define KHF 128                // k-range per k-group in k_attn
#define NCHH (KHF / KC)        // 8 chunks per k-group
#define VP 20                  // padded s_V row stride (floats)

// Per-block partial sums: [Bb*NBLK][2][Cc][TQ] float4 = 16 MB (L2-resident)
__device__ float4 g_part[Bb * NBLK * 2 * Cc * TQ];
__device__ float  g_xu1[Bb * Cc * Tt];    // x_u1 as [b][c][t]
__device__ float  g_M  [Bb * Cc * Tt];    // M[b][c][s]
__device__ float  g_S  [Bb * Tt * Tt];    // sigmoid(product + bias), 2 MB

// cp.async helpers
#define CP_ASYNC16(dst_u32, src_ptr) \
    asm volatile("cp.async.cg.shared.global [%0], [%1], 16;" :: "r"(dst_u32), "l"(src_ptr))
#define CP_COMMIT()  asm volatile("cp.async.commit_group;")
#define CP_WAIT(n)   asm volatile("cp.async.wait_group %0;" :: "n"(n))

// ---------------------------------------------------------------------------
// Kernel 1: single streaming pass over x (256 MB). At DRAM roofline; frozen.
// ---------------------------------------------------------------------------
__global__ __launch_bounds__(256, 3) void k_reduce(
    const float* __restrict__ x,  const float* __restrict__ u1,
    const float* __restrict__ u2, const float* __restrict__ u3)
{
    __shared__ float s_u1[NPB];
    __shared__ float s_u2[Cc * NPB];

    const int tid    = threadIdx.x;
    const int lane   = tid & 31;
    const int warp   = tid >> 5;
    const int qg     = lane & 7;
    const int n_sub  = (lane >> 3) & 1;
    const int c_half = lane >> 4;
    const int q      = warp * 8 + qg;

    const int b  = blockIdx.y;
    const int n0 = blockIdx.x * NPB;

    if (tid < NPB) s_u1[tid] = u1[n0 + tid];
    {
        int c = tid >> 5, nn = tid & 31;
        s_u2[tid] = u2[c * Nn + n0 + nn];
    }
    float c3[4];
#pragma unroll
    for (int cc = 0; cc < 4; cc++) c3[cc] = u3[c_half * 4 + cc];
    __syncthreads();

    const float4* xb = (const float4*)x
                     + ((size_t)b * Nn + n0) * (Cc * TQ)
                     + c_half * 4 * TQ + q;

    float4 ax[4], am[4];
#pragma unroll
    for (int cc = 0; cc < 4; cc++) {
        ax[cc] = make_float4(0.f, 0.f, 0.f, 0.f);
        am[cc] = make_float4(0.f, 0.f, 0.f, 0.f);
    }

#pragma unroll
    for (int i = 0; i < NPB / 2; i++) {
        const int n = i * 2 + n_sub;
        const float4* xn = xb + (size_t)n * (Cc * TQ);

        float4 vals[4];
#pragma unroll
        for (int cc = 0; cc < 4; cc++) vals[cc] = __ldcs(xn + cc * TQ);

        float4 r = make_float4(0.f, 0.f, 0.f, 0.f);
#pragma unroll
        for (int cc = 0; cc < 4; cc++) {
            r.x += vals[cc].x * c3[cc];
            r.y += vals[cc].y * c3[cc];
            r.z += vals[cc].z * c3[cc];
            r.w += vals[cc].w * c3[cc];
        }
        r.x += __shfl_xor_sync(0xffffffffu, r.x, 16);
        r.y += __shfl_xor_sync(0xffffffffu, r.y, 16);
        r.z += __shfl_xor_sync(0xffffffffu, r.z, 16);
        r.w += __shfl_xor_sync(0xffffffffu, r.w, 16);

        const float un = s_u1[n];
#pragma unroll
        for (int cc = 0; cc < 4; cc++) {
            ax[cc].x += vals[cc].x * un;
            ax[cc].y += vals[cc].y * un;
            ax[cc].z += vals[cc].z * un;
            ax[cc].w += vals[cc].w * un;
            const float w = s_u2[(c_half * 4 + cc) * NPB + n];
            am[cc].x += r.x * w;
            am[cc].y += r.y * w;
            am[cc].z += r.z * w;
            am[cc].w += r.w * w;
        }
    }

#pragma unroll
    for (int cc = 0; cc < 4; cc++) {
        ax[cc].x += __shfl_xor_sync(0xffffffffu, ax[cc].x, 8);
        ax[cc].y += __shfl_xor_sync(0xffffffffu, ax[cc].y, 8);
        ax[cc].z += __shfl_xor_sync(0xffffffffu, ax[cc].z, 8);
        ax[cc].w += __shfl_xor_sync(0xffffffffu, ax[cc].w, 8);
        am[cc].x += __shfl_xor_sync(0xffffffffu, am[cc].x, 8);
        am[cc].y += __shfl_xor_sync(0xffffffffu, am[cc].y, 8);
        am[cc].z += __shfl_xor_sync(0xffffffffu, am[cc].z, 8);
        am[cc].w += __shfl_xor_sync(0xffffffffu, am[cc].w, 8);
    }

    if (n_sub == 0) {
        float4* gp = g_part + (size_t)(b * NBLK + blockIdx.x) * (2 * Cc * TQ);
#pragma unroll
        for (int cc = 0; cc < 4; cc++) {
            const int c = c_half * 4 + cc;
            gp[c * TQ + q]           = ax[cc];
            gp[Cc * TQ + c * TQ + q] = am[cc];
        }
    }
}

// ---------------------------------------------------------------------------
// Kernel 2: reduce 128 per-block partials -> g_xu1, g_M.
// ---------------------------------------------------------------------------
__global__ __launch_bounds__(512) void k_reduce2()
{
    __shared__ float4 red[4][128];

    const int t   = threadIdx.x;
    const int tx  = t & 127;
    const int ty  = t >> 7;
    const int idx = blockIdx.x * 128 + tx;
    const int b   = idx >> 10;
    const int rem = idx & 1023;

    const float4* gp = g_part + (size_t)b * NBLK * (2 * Cc * TQ) + rem
                     + (size_t)ty * (NBLK / 4) * (2 * Cc * TQ);
    float4 s = make_float4(0.f, 0.f, 0.f, 0.f);
#pragma unroll 8
    for (int k = 0; k < NBLK / 4; k++) {
        float4 v = gp[(size_t)k * (2 * Cc * TQ)];
        s.x += v.x; s.y += v.y; s.z += v.z; s.w += v.w;
    }
    red[ty][tx] = s;
    __syncthreads();

    if (ty == 0) {
        float4 a = red[0][tx], b2 = red[1][tx], c = red[2][tx], d = red[3][tx];
        s.x = (a.x + b2.x) + (c.x + d.x);
        s.y = (a.y + b2.y) + (c.y + d.y);
        s.z = (a.z + b2.z) + (c.z + d.z);
        s.w = (a.w + b2.w) + (c.w + d.w);
        if (rem < Cc * TQ) ((float4*)g_xu1)[b * (Cc * TQ) + rem] = s;
        else               ((float4*)g_M  )[b * (Cc * TQ) + rem - Cc * TQ] = s;
    }
}

// ---------------------------------------------------------------------------
// Kernel 3: S[b,k,j] = sigmoid( sum_c x_u1[b,c,k]*M[b,c,j] + bias[k,j] )
// ---------------------------------------------------------------------------
__global__ __launch_bounds__(256) void k_sig(const float* __restrict__ bias)
{
    __shared__ __align__(16) float s_M[Cc * Tt];
    __shared__ __align__(16) float s_X[KG * Cc];

    const int j  = threadIdx.x;
    const int b  = blockIdx.y;
    const int k0 = blockIdx.x * KG;

    for (int idx = j; idx < Cc * Tt; idx += 256)
        s_M[idx] = g_M[b * Cc * Tt + idx];
    if (j < KG * Cc) {
        int kl = j >> 3, c = j & 7;
        s_X[kl * Cc + c] = g_xu1[b * Cc * Tt + c * Tt + (k0 + kl)];
    }
    __syncthreads();

    float rm[Cc];
#pragma unroll
    for (int c = 0; c < Cc; c++) rm[c] = s_M[c * Tt + j];

#pragma unroll
    for (int kl = 0; kl < KG; kl++) {
        float4 x0 = *(const float4*)&s_X[kl * Cc + 0];
        float4 x1 = *(const float4*)&s_X[kl * Cc + 4];
        float p = bias[(k0 + kl) * Tt + j];
        p += x0.x * rm[0] + x0.y * rm[1] + x0.z * rm[2] + x0.w * rm[3]
           + x1.x * rm[4] + x1.y * rm[5] + x1.z * rm[6] + x1.w * rm[7];
        float e = __expf(-p);
        g_S[b * Tt * Tt + (k0 + kl) * Tt + j] = __frcp_rn(1.f + e);
    }
}

// ---------------------------------------------------------------------------
// Kernel 4: E = v @ S per batch, fused softmax. 512 threads = 2 k-groups of
// 256; each group does half the k-range with the 4x4 register tile, writes a
// partial-E smem plane; softmax combines the two planes. 16 warps/block.
// ---------------------------------------------------------------------------
__global__ __launch_bounds__(512, 1) void k_attn(
    const float* __restrict__ v, float* __restrict__ out)
{
    __shared__ __align__(16) float s_S[2][2][KC * Tt];  // [kg][buf], 64 KB
    __shared__ __align__(16) float s_V[Tt * VP];        // 20 KB, [k][il]

    float* s_E = &s_S[0][0][0];   // 2 x 16 KB partial-E planes (reuse s_S[0])

    const int tid = threadIdx.x;
    const int kg  = tid >> 8;          // k-group 0/1
    const int t   = tid & 255;
    const int jq  = t & 63;            // j-quad: cols jq*4..+3
    const int rh  = t >> 6;            // row-group: rows rh*4..+3
    const int j4  = jq * 4;
    const int b   = blockIdx.y;
    const int i0  = blockIdx.x * TI;

    const char* Sg = (const char*)(g_S + (size_t)b * Tt * Tt + (size_t)kg * KHF * Tt);
    unsigned int sb[2];
    sb[0] = (unsigned int)__cvta_generic_to_shared(&s_S[kg][0][0]);
    sb[1] = (unsigned int)__cvta_generic_to_shared(&s_S[kg][1][0]);

    // stage chunk 0 for this k-group (16 KB: 256 threads x 4 x 16B)
#pragma unroll
    for (int tq = 0; tq < 4; tq++)
        CP_ASYNC16(sb[0] + tq * 4096 + t * 16, Sg + tq * 4096 + t * 16);
    CP_COMMIT();

    // stage v: s_V[k*VP + il]; thread handles k = t, il in [kg*8, kg*8+8)
#pragma unroll
    for (int il = 0; il < TI / 2; il++)
        s_V[t * VP + kg * 8 + il] = v[(i0 + kg * 8 + il) * Tt + t];

    float acc[16];
#pragma unroll
    for (int a = 0; a < 16; a++) acc[a] = 0.f;

    for (int ch = 0; ch < NCHH; ch++) {
        if (ch + 1 < NCHH) {
            const char* src = Sg + (size_t)(ch + 1) * KC * Tt * 4;
            const unsigned int dst = sb[(ch + 1) & 1];
#pragma unroll
            for (int tq = 0; tq < 4; tq++)
                CP_ASYNC16(dst + tq * 4096 + t * 16, src + tq * 4096 + t * 16);
            CP_COMMIT();
            CP_WAIT(1);
        } else {
            CP_WAIT(0);
        }
        __syncthreads();

        const float* Sc = &s_S[kg][ch & 1][0];
#pragma unroll
        for (int kk = 0; kk < KC; kk++) {
            const int k = kg * KHF + ch * KC + kk;
            float4 s4 = *(const float4*)&Sc[kk * Tt + j4];
            float4 vv = *(const float4*)&s_V[k * VP + rh * 4];  // broadcast

            acc[0]  += vv.x * s4.x;  acc[1]  += vv.x * s4.y;
            acc[2]  += vv.x * s4.z;  acc[3]  += vv.x * s4.w;
            acc[4]  += vv.y * s4.x;  acc[5]  += vv.y * s4.y;
            acc[6]  += vv.y * s4.z;  acc[7]  += vv.y * s4.w;
            acc[8]  += vv.z * s4.x;  acc[9]  += vv.z * s4.y;
            acc[10] += vv.z * s4.z;  acc[11] += vv.z * s4.w;
            acc[12] += vv.w * s4.x;  acc[13] += vv.w * s4.y;
            acc[14] += vv.w * s4.z;  acc[15] += vv.w * s4.w;
        }
        __syncthreads();
    }

    // write partial E planes (s_E aliases s_S[0]; all buffers now dead)
    float* Ep = s_E + kg * (TI * Tt);
#pragma unroll
    for (int r = 0; r < 4; r++)
        *(float4*)&Ep[(rh * 4 + r) * Tt + j4] =
            make_float4(acc[r * 4], acc[r * 4 + 1], acc[r * 4 + 2], acc[r * 4 + 3]);
    __syncthreads();

    // Softmax: 16 warps, warp w owns row w; combine the two partial planes.
    const int w = tid >> 5, lane = tid & 31;
    const float* E0 = s_E + w * Tt;
    const float* E1 = s_E + TI * Tt + w * Tt;

    float e[Tt / 32];
    float m = -1e30f;
#pragma unroll
    for (int qi = 0; qi < Tt / 32; qi++) {
        e[qi] = E0[qi * 32 + lane] + E1[qi * 32 + lane];
        m = fmaxf(m, e[qi]);
    }
#pragma unroll
    for (int off = 16; off > 0; off >>= 1)
        m = fmaxf(m, __shfl_xor_sync(0xffffffffu, m, off));

    float sum = 0.f;
#pragma unroll
    for (int qi = 0; qi < Tt / 32; qi++) {
        e[qi] = __expf(e[qi] - m);
        sum += e[qi];
    }
#pragma unroll
    for (int off = 16; off > 0; off >>= 1)
        sum += __shfl_xor_sync(0xffffffffu, sum, off);

    const float inv = __frcp_rn(sum);
    const size_t o = ((size_t)b * Tt + (i0 + w)) * Tt;
#pragma unroll
    for (int qi = 0; qi < Tt / 32; qi++)
        out[o + qi * 32 + lane] = e[qi] * inv;
}

// ---------------------------------------------------------------------------
extern "C" void kernel_launch(void* const* d_in, const int* in_sizes, int n_in,
                              void* d_out, int out_size)
{
    const float* x  = (const float*)d_in[0];
    const float* u1 = (const float*)d_in[1];
    const float* u2 = (const float*)d_in[2];
    const float* u3 = (const float*)d_in[3];
    const float* bb = (const float*)d_in[4];
    const float* v  = (const float*)d_in[5];
    float* out = (float*)d_out;

    dim3 g1(NBLK, Bb);              // 1024 blocks
    k_reduce<<<g1, 256>>>(x, u1, u2, u3);

    k_reduce2<<<64, 512>>>();

    dim3 g2(Tt / KG, Bb);           // 256 blocks
    k_sig<<<g2, 256>>>(bb);

    dim3 g3(Tt / TI, Bb);           // 128 blocks, 512 threads
    k_attn<<<g3, 512>>>(v, out);
}

// round 10
// speedup vs baseline: 1.0096x; 1.0096x over previous
#include <cuda_runtime.h>
#include <cstdint>

#define Bb 8
#define Nn 4096
#define Cc 8
#define Tt 256
#define NPB 32                 // n-values per block in k_reduce
#define NBLK (Nn / NPB)        // 128 n-blocks per batch
#define TQ (Tt / 4)            // 64 float4 quads over t
#define KG 8                   // k's per block in k_sig
#define TI 16                  // output rows per block in k_attn
#define KC 8                   // k-rows per staged S chunk in k_attn
#define KHF 128                // k-range per k-group in k_attn
#define NCHH (KHF / KC)        // 16 chunks per k-group
#define VP 20                  // padded s_V row stride (floats)

// Per-block partial sums: [Bb*NBLK][2][Cc][TQ] float4 = 16 MB (L2-resident)
__device__ float4 g_part[Bb * NBLK * 2 * Cc * TQ];
__device__ float  g_xu1[Bb * Cc * Tt];    // x_u1 as [b][c][t]
__device__ float  g_M  [Bb * Cc * Tt];    // M[b][c][s]
__device__ float  g_S  [Bb * Tt * Tt];    // sigmoid(product + bias), 2 MB

// cp.async helpers
#define CP_ASYNC16(dst_u32, src_ptr) \
    asm volatile("cp.async.cg.shared.global [%0], [%1], 16;" :: "r"(dst_u32), "l"(src_ptr))
#define CP_COMMIT()  asm volatile("cp.async.commit_group;")
#define CP_WAIT(n)   asm volatile("cp.async.wait_group %0;" :: "n"(n))

// ---------------------------------------------------------------------------
// Kernel 1: single streaming pass over x (256 MB).
// Lane layout: lane = cq*8 + qg. Thread owns c-pair {2cq, 2cq+1}, quad q.
// All lanes iterate every n; u3-dot completed via shfl_xor(8,16).
// Low-reg (~60) -> 3 blocks/SM -> more loads in flight.
// ---------------------------------------------------------------------------
__global__ __launch_bounds__(256, 3) void k_reduce(
    const float* __restrict__ x,  const float* __restrict__ u1,
    const float* __restrict__ u2, const float* __restrict__ u3)
{
    __shared__ float s_u1[NPB];
    __shared__ float s_u2[Cc * NPB];

    const int tid  = threadIdx.x;
    const int lane = tid & 31;
    const int warp = tid >> 5;
    const int qg   = lane & 7;
    const int cq   = lane >> 3;               // 0..3 -> c pair {2cq, 2cq+1}
    const int q    = warp * 8 + qg;           // 0..63

    const int b  = blockIdx.y;
    const int n0 = blockIdx.x * NPB;

    if (tid < NPB) s_u1[tid] = u1[n0 + tid];
    {   // Cc*NPB == 256 == blockDim
        int c = tid >> 5, nn = tid & 31;
        s_u2[tid] = u2[c * Nn + n0 + nn];
    }
    const float c30 = u3[2 * cq];
    const float c31 = u3[2 * cq + 1];
    __syncthreads();

    const float4* xb = (const float4*)x
                     + ((size_t)b * Nn + n0) * (Cc * TQ)
                     + (2 * cq) * TQ + q;

    float4 ax0 = make_float4(0.f, 0.f, 0.f, 0.f), ax1 = ax0;
    float4 am0 = ax0, am1 = ax0;

#pragma unroll
    for (int n = 0; n < NPB; n++) {
        const float4* xn = xb + (size_t)n * (Cc * TQ);
        float4 v0 = __ldcs(xn);
        float4 v1 = __ldcs(xn + TQ);

        float4 r;
        r.x = v0.x * c30 + v1.x * c31;
        r.y = v0.y * c30 + v1.y * c31;
        r.z = v0.z * c30 + v1.z * c31;
        r.w = v0.w * c30 + v1.w * c31;
        // complete the c-sum across the 4 cq groups
        r.x += __shfl_xor_sync(0xffffffffu, r.x, 8);
        r.y += __shfl_xor_sync(0xffffffffu, r.y, 8);
        r.z += __shfl_xor_sync(0xffffffffu, r.z, 8);
        r.w += __shfl_xor_sync(0xffffffffu, r.w, 8);
        r.x += __shfl_xor_sync(0xffffffffu, r.x, 16);
        r.y += __shfl_xor_sync(0xffffffffu, r.y, 16);
        r.z += __shfl_xor_sync(0xffffffffu, r.z, 16);
        r.w += __shfl_xor_sync(0xffffffffu, r.w, 16);

        const float un = s_u1[n];
        ax0.x += v0.x * un;  ax0.y += v0.y * un;
        ax0.z += v0.z * un;  ax0.w += v0.w * un;
        ax1.x += v1.x * un;  ax1.y += v1.y * un;
        ax1.z += v1.z * un;  ax1.w += v1.w * un;

        const float w0 = s_u2[(2 * cq) * NPB + n];
        const float w1 = s_u2[(2 * cq + 1) * NPB + n];
        am0.x += r.x * w0;  am0.y += r.y * w0;
        am0.z += r.z * w0;  am0.w += r.w * w0;
        am1.x += r.x * w1;  am1.y += r.y * w1;
        am1.z += r.z * w1;  am1.w += r.w * w1;
    }

    float4* gp = g_part + (size_t)(b * NBLK + blockIdx.x) * (2 * Cc * TQ);
    gp[(2 * cq) * TQ + q]               = ax0;
    gp[(2 * cq + 1) * TQ + q]           = ax1;
    gp[Cc * TQ + (2 * cq) * TQ + q]     = am0;
    gp[Cc * TQ + (2 * cq + 1) * TQ + q] = am1;
}

// ---------------------------------------------------------------------------
// Kernel 2: reduce 128 per-block partials -> g_xu1, g_M.
// ---------------------------------------------------------------------------
__global__ __launch_bounds__(512) void k_reduce2()
{
    __shared__ float4 red[4][128];

    const int t   = threadIdx.x;
    const int tx  = t & 127;
    const int ty  = t >> 7;
    const int idx = blockIdx.x * 128 + tx;
    const int b   = idx >> 10;
    const int rem = idx & 1023;

    const float4* gp = g_part + (size_t)b * NBLK * (2 * Cc * TQ) + rem
                     + (size_t)ty * (NBLK / 4) * (2 * Cc * TQ);
    float4 s = make_float4(0.f, 0.f, 0.f, 0.f);
#pragma unroll 8
    for (int k = 0; k < NBLK / 4; k++) {
        float4 v = gp[(size_t)k * (2 * Cc * TQ)];
        s.x += v.x; s.y += v.y; s.z += v.z; s.w += v.w;
    }
    red[ty][tx] = s;
    __syncthreads();

    if (ty == 0) {
        float4 a = red[0][tx], b2 = red[1][tx], c = red[2][tx], d = red[3][tx];
        s.x = (a.x + b2.x) + (c.x + d.x);
        s.y = (a.y + b2.y) + (c.y + d.y);
        s.z = (a.z + b2.z) + (c.z + d.z);
        s.w = (a.w + b2.w) + (c.w + d.w);
        if (rem < Cc * TQ) ((float4*)g_xu1)[b * (Cc * TQ) + rem] = s;
        else               ((float4*)g_M  )[b * (Cc * TQ) + rem - Cc * TQ] = s;
    }
}

// ---------------------------------------------------------------------------
// Kernel 3: S[b,k,j] = sigmoid( sum_c x_u1[b,c,k]*M[b,c,j] + bias[k,j] )
// ---------------------------------------------------------------------------
__global__ __launch_bounds__(256) void k_sig(const float* __restrict__ bias)
{
    __shared__ __align__(16) float s_M[Cc * Tt];
    __shared__ __align__(16) float s_X[KG * Cc];

    const int j  = threadIdx.x;
    const int b  = blockIdx.y;
    const int k0 = blockIdx.x * KG;

    for (int idx = j; idx < Cc * Tt; idx += 256)
        s_M[idx] = g_M[b * Cc * Tt + idx];
    if (j < KG * Cc) {
        int kl = j >> 3, c = j & 7;
        s_X[kl * Cc + c] = g_xu1[b * Cc * Tt + c * Tt + (k0 + kl)];
    }
    __syncthreads();

    float rm[Cc];
#pragma unroll
    for (int c = 0; c < Cc; c++) rm[c] = s_M[c * Tt + j];

#pragma unroll
    for (int kl = 0; kl < KG; kl++) {
        float4 x0 = *(const float4*)&s_X[kl * Cc + 0];
        float4 x1 = *(const float4*)&s_X[kl * Cc + 4];
        float p = bias[(k0 + kl) * Tt + j];
        p += x0.x * rm[0] + x0.y * rm[1] + x0.z * rm[2] + x0.w * rm[3]
           + x1.x * rm[4] + x1.y * rm[5] + x1.z * rm[6] + x1.w * rm[7];
        float e = __expf(-p);
        g_S[b * Tt * Tt + (k0 + kl) * Tt + j] = __frcp_rn(1.f + e);
    }
}

// ---------------------------------------------------------------------------
// Kernel 4: E = v @ S per batch, fused softmax. 512 threads = 2 k-groups;
// KC=8 chunks keep smem at ~52 KB -> 2 blocks/SM (32 warps).
// ---------------------------------------------------------------------------
__global__ __launch_bounds__(512, 2) void k_attn(
    const float* __restrict__ v, float* __restrict__ out)
{
    __shared__ __align__(16) float s_S[2][2][KC * Tt];  // [kg][buf], 32 KB
    __shared__ __align__(16) float s_V[Tt * VP];        // 20 KB, [k][il]

    float* s_E = &s_S[0][0][0];   // 2 x 16 KB partial-E planes (alias all s_S)

    const int tid = threadIdx.x;
    const int kg  = tid >> 8;          // k-group 0/1
    const int t   = tid & 255;
    const int jq  = t & 63;            // j-quad: cols jq*4..+3
    const int rh  = t >> 6;            // row-group: rows rh*4..+3
    const int j4  = jq * 4;
    const int b   = blockIdx.y;
    const int i0  = blockIdx.x * TI;

    const char* Sg = (const char*)(g_S + (size_t)b * Tt * Tt + (size_t)kg * KHF * Tt);
    unsigned int sb[2];
    sb[0] = (unsigned int)__cvta_generic_to_shared(&s_S[kg][0][0]);
    sb[1] = (unsigned int)__cvta_generic_to_shared(&s_S[kg][1][0]);

    // stage chunk 0 for this k-group (8 KB: 256 threads x 2 x 16B)
#pragma unroll
    for (int tq = 0; tq < 2; tq++)
        CP_ASYNC16(sb[0] + tq * 4096 + t * 16, Sg + tq * 4096 + t * 16);
    CP_COMMIT();

    // stage v: s_V[k*VP + il]; thread handles k = t, il in [kg*8, kg*8+8)
#pragma unroll
    for (int il = 0; il < TI / 2; il++)
        s_V[t * VP + kg * 8 + il] = v[(i0 + kg * 8 + il) * Tt + t];

    float acc[16];
#pragma unroll
    for (int a = 0; a < 16; a++) acc[a] = 0.f;

    for (int ch = 0; ch < NCHH; ch++) {
        if (ch + 1 < NCHH) {
            const char* src = Sg + (size_t)(ch + 1) * KC * Tt * 4;
            const unsigned int dst = sb[(ch + 1) & 1];
#pragma unroll
            for (int tq = 0; tq < 2; tq++)
                CP_ASYNC16(dst + tq * 4096 + t * 16, src + tq * 4096 + t * 16);
            CP_COMMIT();
            CP_WAIT(1);
        } else {
            CP_WAIT(0);
        }
        __syncthreads();

        const float* Sc = &s_S[kg][ch & 1][0];
#pragma unroll
        for (int kk = 0; kk < KC; kk++) {
            const int k = kg * KHF + ch * KC + kk;
            float4 s4 = *(const float4*)&Sc[kk * Tt + j4];
            float4 vv = *(const float4*)&s_V[k * VP + rh * 4];  // broadcast

            acc[0]  += vv.x * s4.x;  acc[1]  += vv.x * s4.y;
            acc[2]  += vv.x * s4.z;  acc[3]  += vv.x * s4.w;
            acc[4]  += vv.y * s4.x;  acc[5]  += vv.y * s4.y;
            acc[6]  += vv.y * s4.z;  acc[7]  += vv.y * s4.w;
            acc[8]  += vv.z * s4.x;  acc[9]  += vv.z * s4.y;
            acc[10] += vv.z * s4.z;  acc[11] += vv.z * s4.w;
            acc[12] += vv.w * s4.x;  acc[13] += vv.w * s4.y;
            acc[14] += vv.w * s4.z;  acc[15] += vv.w * s4.w;
        }
        __syncthreads();
    }

    // write partial E planes (alias the now-dead s_S buffers)
    float* Ep = s_E + kg * (TI * Tt);
#pragma unroll
    for (int r = 0; r < 4; r++)
        *(float4*)&Ep[(rh * 4 + r) * Tt + j4] =
            make_float4(acc[r * 4], acc[r * 4 + 1], acc[r * 4 + 2], acc[r * 4 + 3]);
    __syncthreads();

    // Softmax: 16 warps, warp w owns row w; combine the two partial planes.
    const int w = tid >> 5, lane = tid & 31;
    const float* E0 = s_E + w * Tt;
    const float* E1 = s_E + TI * Tt + w * Tt;

    float e[Tt / 32];
    float m = -1e30f;
#pragma unroll
    for (int qi = 0; qi < Tt / 32; qi++) {
        e[qi] = E0[qi * 32 + lane] + E1[qi * 32 + lane];
        m = fmaxf(m, e[qi]);
    }
#pragma unroll
    for (int off = 16; off > 0; off >>= 1)
        m = fmaxf(m, __shfl_xor_sync(0xffffffffu, m, off));

    float sum = 0.f;
#pragma unroll
    for (int qi = 0; qi < Tt / 32; qi++) {
        e[qi] = __expf(e[qi] - m);
        sum += e[qi];
    }
#pragma unroll
    for (int off = 16; off > 0; off >>= 1)
        sum += __shfl_xor_sync(0xffffffffu, sum, off);

    const float inv = __frcp_rn(sum);
    const size_t o = ((size_t)b * Tt + (i0 + w)) * Tt;
#pragma unroll
    for (int qi = 0; qi < Tt / 32; qi++)
        out[o + qi * 32 + lane] = e[qi] * inv;
}

// ---------------------------------------------------------------------------
extern "C" void kernel_launch(void* const* d_in, const int* in_sizes, int n_in,
                              void* d_out, int out_size)
{
    const float* x  = (const float*)d_in[0];
    const float* u1 = (const float*)d_in[1];
    const float* u2 = (const float*)d_in[2];
    const float* u3 = (const float*)d_in[3];
    const float* bb = (const float*)d_in[4];
    const float* v  = (const float*)d_in[5];
    float* out = (float*)d_out;

    dim3 g1(NBLK, Bb);              // 1024 blocks
    k_reduce<<<g1, 256>>>(x, u1, u2, u3);

    k_reduce2<<<64, 512>>>();

    dim3 g2(Tt / KG, Bb);           // 256 blocks
    k_sig<<<g2, 256>>>(bb);

    dim3 g3(Tt / TI, Bb);           // 128 blocks, 512 threads
    k_attn<<<g3, 512>>>(v, out);
}